// round 7
// baseline (speedup 1.0000x reference)
#include <cuda_runtime.h>
#include <cstdint>

// one_hot: label (4096x4096 int32) -> out (8, 4096, 4096) float32
// out[n, h, w] = (label[h, w] == n) ? 1.0f : 0.0f
//
// Pure HBM streaming: 64 MiB read + 512 MiB write (~75.5us floor at 8 TB/s).
// R1 (1 int4/thread, .cs):     94.3us, DRAM=70.8%
// R2 (adjacent 2/thread):     144us   (broke per-instruction coalescing)
// R3 (strided 2/thread):       97.2us (queue depth: no effect)
// R4 (v8.f32 .cs stores):      93.8us, DRAM=71.3% (issue density: no effect)
// R5: SAME as R4 but default write-back stores (no .cs). Hypothesis: evict-
//     first drains L2 eagerly/fragmented; write-back lets the DRAM scheduler
//     batch rows. Single-variable change.

#define H 4096
#define W 4096
#define NCLS 8
#define HW (H * W)             // 16777216
#define LPT 8                  // labels (and floats per plane) per thread
#define BLK 256
#define NTHREADS (HW / LPT)    // 2097152
#define NBLOCKS (NTHREADS / BLK)   // 8192

__device__ __forceinline__ void st256(float* p, const float* v)
{
    asm volatile(
        "st.global.v8.f32 [%0], {%1,%2,%3,%4,%5,%6,%7,%8};"
        :: "l"(p),
           "f"(v[0]), "f"(v[1]), "f"(v[2]), "f"(v[3]),
           "f"(v[4]), "f"(v[5]), "f"(v[6]), "f"(v[7])
        : "memory");
}

__global__ void __launch_bounds__(BLK) onehot_kernel(
    const int4* __restrict__ lab4, float* __restrict__ out)
{
    // thread handles 8 consecutive labels: elements [8*g, 8*g+8)
    unsigned g = blockIdx.x * (unsigned)BLK + threadIdx.x;
    const int4* p = lab4 + (size_t)g * 2;
    int4 a = __ldcs(p);
    int4 b = __ldcs(p + 1);
    int l[8] = { a.x, a.y, a.z, a.w, b.x, b.y, b.z, b.w };

    size_t base = (size_t)g * LPT;
#pragma unroll
    for (int n = 0; n < NCLS; n++) {
        float v[8];
#pragma unroll
        for (int k = 0; k < 8; k++)
            v[k] = (l[k] == n) ? 1.0f : 0.0f;
        st256(out + (size_t)n * HW + base, v);
    }
}

extern "C" void kernel_launch(void* const* d_in, const int* in_sizes, int n_in,
                              void* d_out, int out_size)
{
    const int4* lab4 = (const int4*)d_in[0];
    float* out = (float*)d_out;
    onehot_kernel<<<NBLOCKS, BLK>>>(lab4, out);
}

// round 8
// speedup vs baseline: 1.0033x; 1.0033x over previous
#include <cuda_runtime.h>
#include <cstdint>

// one_hot: label (4096x4096 int32) -> out (8, 4096, 4096) float32
// out[n, h, w] = (label[h, w] == n) ? 1.0f : 0.0f
//
// Pure HBM streaming: 64 MiB read + 512 MiB write (~75.5us floor at 8 TB/s).
// R1 (1 int4/thread, .cs):     94.3us, DRAM=70.8%
// R2 (adjacent 2/thread):     144us   (broke per-instruction coalescing)
// R3 (strided 2/thread):       97.2us (queue depth: no effect)
// R4 (v8.f32 .cs stores):      93.8us, DRAM=71.3% (issue density: no effect)
// R5: SAME as R4 but default write-back stores (no .cs). Hypothesis: evict-
//     first drains L2 eagerly/fragmented; write-back lets the DRAM scheduler
//     batch rows. Single-variable change.

#define H 4096
#define W 4096
#define NCLS 8
#define HW (H * W)             // 16777216
#define LPT 8                  // labels (and floats per plane) per thread
#define BLK 256
#define NTHREADS (HW / LPT)    // 2097152
#define NBLOCKS (NTHREADS / BLK)   // 8192

__device__ __forceinline__ void st256(float* p, const float* v)
{
    asm volatile(
        "st.global.v8.f32 [%0], {%1,%2,%3,%4,%5,%6,%7,%8};"
        :: "l"(p),
           "f"(v[0]), "f"(v[1]), "f"(v[2]), "f"(v[3]),
           "f"(v[4]), "f"(v[5]), "f"(v[6]), "f"(v[7])
        : "memory");
}

__global__ void __launch_bounds__(BLK) onehot_kernel(
    const int4* __restrict__ lab4, float* __restrict__ out)
{
    // thread handles 8 consecutive labels: elements [8*g, 8*g+8)
    unsigned g = blockIdx.x * (unsigned)BLK + threadIdx.x;
    const int4* p = lab4 + (size_t)g * 2;
    int4 a = __ldcs(p);
    int4 b = __ldcs(p + 1);
    int l[8] = { a.x, a.y, a.z, a.w, b.x, b.y, b.z, b.w };

    size_t base = (size_t)g * LPT;
#pragma unroll
    for (int n = 0; n < NCLS; n++) {
        float v[8];
#pragma unroll
        for (int k = 0; k < 8; k++)
            v[k] = (l[k] == n) ? 1.0f : 0.0f;
        st256(out + (size_t)n * HW + base, v);
    }
}

extern "C" void kernel_launch(void* const* d_in, const int* in_sizes, int n_in,
                              void* d_out, int out_size)
{
    const int4* lab4 = (const int4*)d_in[0];
    float* out = (float*)d_out;
    onehot_kernel<<<NBLOCKS, BLK>>>(lab4, out);
}